// round 1
// baseline (speedup 1.0000x reference)
#include <cuda_runtime.h>
#include <math.h>

#define H 768
#define H4 (H/4)
#define SLEN 512
#define BATCH 8
#define M_ROWS (BATCH*SLEN)        // 4096
#define NELEM (BATCH*SLEN*H)       // 3145728
#define NVEC (NELEM/4)             // 786432

// ---- device globals (scratch; no allocation allowed) ----
__device__ int   g_index;
__device__ float g_wsel;
__device__ float g_sum[H];
__device__ float g_sumsq[H];
__device__ float g_y[NELEM];        // conv output scratch [b,s,o]
__device__ float g_y1[NELEM];       // depthwise output scratch [b,s,c]
__device__ float g_wpack[H*H*7];    // packed weights [(dk*H + i)*H + o]

// =====================================================================
// Gate: gumbel straight-through argmax. Also zeroes the BN accumulators.
// =====================================================================
__global__ void gate_kernel(const float* __restrict__ arch,
                            const float* __restrict__ u) {
    int t = threadIdx.x;
    for (int c = t; c < H; c += blockDim.x) { g_sum[c] = 0.f; g_sumsq[c] = 0.f; }
    if (t == 0) {
        float a[10], l[10], p[10];
        float m = -1e30f;
        for (int j = 0; j < 10; j++) { a[j] = arch[j]; m = fmaxf(m, a[j]); }
        float se = 0.f;
        for (int j = 0; j < 10; j++) se += expf(a[j] - m);
        float lse = logf(se);
        float m2 = -1e30f;
        for (int j = 0; j < 10; j++) {
            float uc = u[j];
            uc = fminf(fmaxf(uc, 1e-9f), 1.0f - 1e-9f);
            float g = -logf(-logf(uc));
            l[j] = ((a[j] - m - lse) + g) * 0.1f;   // / TEM (=10)
            m2 = fmaxf(m2, l[j]);
        }
        float s2 = 0.f;
        for (int j = 0; j < 10; j++) { p[j] = expf(l[j] - m2); s2 += p[j]; }
        int best = 0; float bp = -1.f;
        for (int j = 0; j < 10; j++) {
            p[j] /= s2;
            if (p[j] > bp) { bp = p[j]; best = j; }
        }
        g_index = best;
        // hardwts[best] = (1 - p) + p ; all other entries exactly 0, so
        // sum(w) - w_sel == 0 and out = w_sel * op(x) + x.
        g_wsel = (1.0f - bp) + bp;
    }
}

// =====================================================================
// Branches 0,1,2,9: none / avg_pool3 / max_pool3 / skip (elementwise)
// =====================================================================
__global__ void simple_kernel(const float* __restrict__ x, float* __restrict__ out) {
    int idx = g_index;
    if (!(idx == 0 || idx == 1 || idx == 2 || idx == 9)) return;
    float w = g_wsel;
    const float4* x4 = (const float4*)x;
    float4* o4 = (float4*)out;
    for (int v = blockIdx.x * blockDim.x + threadIdx.x; v < NVEC;
         v += gridDim.x * blockDim.x) {
        int c4 = v % H4;
        int s  = (v / H4) % SLEN;
        int b  = v / (H4 * SLEN);
        float4 xc = x4[v];
        float4 val;
        if (idx == 0) {
            val = make_float4(0.f, 0.f, 0.f, 0.f);
        } else if (idx == 9) {
            val = xc;
        } else {
            long base = (long)(b * SLEN) * H4 + c4;
            float4 xm = make_float4(0.f, 0.f, 0.f, 0.f);
            float4 xp = make_float4(0.f, 0.f, 0.f, 0.f);
            bool hm = (s > 0), hp = (s < SLEN - 1);
            if (hm) xm = x4[base + (long)(s - 1) * H4];
            if (hp) xp = x4[base + (long)(s + 1) * H4];
            if (idx == 1) {       // avg, count_include_pad
                const float inv3 = 1.f / 3.f;
                val.x = (xm.x + xc.x + xp.x) * inv3;
                val.y = (xm.y + xc.y + xp.y) * inv3;
                val.z = (xm.z + xc.z + xp.z) * inv3;
                val.w = (xm.w + xc.w + xp.w) * inv3;
            } else {              // max, -inf pad -> only valid neighbors
                val = xc;
                if (hm) { val.x = fmaxf(val.x, xm.x); val.y = fmaxf(val.y, xm.y);
                          val.z = fmaxf(val.z, xm.z); val.w = fmaxf(val.w, xm.w); }
                if (hp) { val.x = fmaxf(val.x, xp.x); val.y = fmaxf(val.y, xp.y);
                          val.z = fmaxf(val.z, xp.z); val.w = fmaxf(val.w, xp.w); }
            }
        }
        float4 r;
        r.x = w * val.x + xc.x;
        r.y = w * val.y + xc.y;
        r.z = w * val.z + xc.z;
        r.w = w * val.w + xc.w;
        o4[v] = r;
    }
}

// =====================================================================
// Branches 6,7,8 step 1: depthwise dilated conv (dilation=2, pad=k-1)
// y1[b,s,c] = sum_dk wd[c,dk] * relu(x[b, s+2dk-(k-1), c])
// =====================================================================
__global__ void depthwise_kernel(const float* __restrict__ x,
                                 const float* __restrict__ wd3,
                                 const float* __restrict__ wd5,
                                 const float* __restrict__ wd7) {
    int idx = g_index;
    if (idx < 6 || idx > 8) return;
    int k = 3 + 2 * (idx - 6);
    const float* wd = (idx == 6) ? wd3 : ((idx == 7) ? wd5 : wd7);
    const float4* x4 = (const float4*)x;
    float4* y14 = (float4*)g_y1;
    for (int v = blockIdx.x * blockDim.x + threadIdx.x; v < NVEC;
         v += gridDim.x * blockDim.x) {
        int c4 = v % H4;
        int s  = (v / H4) % SLEN;
        int b  = v / (H4 * SLEN);
        int c0 = c4 * 4;
        float4 acc = make_float4(0.f, 0.f, 0.f, 0.f);
        for (int dk = 0; dk < k; dk++) {
            int s2 = s + 2 * dk - (k - 1);
            if (s2 < 0 || s2 >= SLEN) continue;
            float4 xv = x4[(long)(b * SLEN + s2) * H4 + c4];
            xv.x = fmaxf(xv.x, 0.f); xv.y = fmaxf(xv.y, 0.f);
            xv.z = fmaxf(xv.z, 0.f); xv.w = fmaxf(xv.w, 0.f);
            acc.x += wd[(c0 + 0) * k + dk] * xv.x;
            acc.y += wd[(c0 + 1) * k + dk] * xv.y;
            acc.z += wd[(c0 + 2) * k + dk] * xv.z;
            acc.w += wd[(c0 + 3) * k + dk] * xv.w;
        }
        y14[v] = acc;
    }
}

// =====================================================================
// Weight pack: [(o*H+i)*taps+dk] -> [(dk*H+i)*H+o] (coalesced GEMM B)
// =====================================================================
__global__ void pack_kernel(const float* __restrict__ w3,
                            const float* __restrict__ w5,
                            const float* __restrict__ w7,
                            const float* __restrict__ p3,
                            const float* __restrict__ p5,
                            const float* __restrict__ p7) {
    int idx = g_index;
    if (idx < 3 || idx > 8) return;
    const float* W; int taps;
    switch (idx) {
        case 3: W = w3; taps = 3; break;
        case 4: W = w5; taps = 5; break;
        case 5: W = w7; taps = 7; break;
        case 6: W = p3; taps = 1; break;
        case 7: W = p5; taps = 1; break;
        default: W = p7; taps = 1; break;
    }
    int total = H * H * taps;
    for (int e = blockIdx.x * blockDim.x + threadIdx.x; e < total;
         e += gridDim.x * blockDim.x) {
        int o  = e % H;
        int i  = (e / H) % H;
        int dk = e / (H * H);
        g_wpack[e] = W[(o * H + i) * taps + dk];
    }
}

// =====================================================================
// GEMM: Y[(b,s), o] = sum_dk sum_i act(A[(b,s+dk-pad), i]) * W[o,i,dk]
// nor_conv (idx 3..5): A = relu(x), taps=k, pad=k/2
// pointwise (idx 6..8): A = g_y1, taps=1
// Tile 64x64, BK=16, 256 threads, 4x4 per thread.
// =====================================================================
__global__ void gemm_kernel(const float* __restrict__ x) {
    int idx = g_index;
    if (idx < 3 || idx > 8) return;
    bool is_nor = (idx <= 5);
    int taps = is_nor ? (3 + 2 * (idx - 3)) : 1;
    int pad  = is_nor ? (taps >> 1) : 0;
    const float* A = is_nor ? x : (const float*)g_y1;

    __shared__ float As[16][64];
    __shared__ float Bs[16][64];

    int tid = threadIdx.x;
    int bm = blockIdx.x * 64, bn = blockIdx.y * 64;
    int tm = tid >> 4, tn = tid & 15;

    float acc[4][4] = {};

    int ar = tid & 63;           // A row within tile
    int ac = (tid >> 6) << 2;    // 4 consecutive k's
    int grow = bm + ar;
    int bb = grow >> 9, ss = grow & 511;
    int bkk = tid >> 4;          // B: k index
    int boc = (tid & 15) << 2;   // B: 4 consecutive o's

    for (int dk = 0; dk < taps; dk++) {
        int s2 = ss + dk - pad;
        bool valid = (s2 >= 0 && s2 < SLEN);
        const float* arow = A + (long)((bb << 9) + s2) * H;
        const float* bbase = g_wpack + (long)dk * H * H;
        for (int kt = 0; kt < H; kt += 16) {
            if (valid) {
                float4 v = *(const float4*)(arow + kt + ac);
                if (is_nor) {
                    v.x = fmaxf(v.x, 0.f); v.y = fmaxf(v.y, 0.f);
                    v.z = fmaxf(v.z, 0.f); v.w = fmaxf(v.w, 0.f);
                }
                As[ac][ar] = v.x; As[ac + 1][ar] = v.y;
                As[ac + 2][ar] = v.z; As[ac + 3][ar] = v.w;
            } else {
                As[ac][ar] = 0.f; As[ac + 1][ar] = 0.f;
                As[ac + 2][ar] = 0.f; As[ac + 3][ar] = 0.f;
            }
            float4 w4 = *(const float4*)(bbase + (long)(kt + bkk) * H + bn + boc);
            Bs[bkk][boc] = w4.x; Bs[bkk][boc + 1] = w4.y;
            Bs[bkk][boc + 2] = w4.z; Bs[bkk][boc + 3] = w4.w;
            __syncthreads();
            #pragma unroll
            for (int kk = 0; kk < 16; kk++) {
                float a0 = As[kk][tm * 4 + 0];
                float a1 = As[kk][tm * 4 + 1];
                float a2 = As[kk][tm * 4 + 2];
                float a3 = As[kk][tm * 4 + 3];
                float b0 = Bs[kk][tn * 4 + 0];
                float b1 = Bs[kk][tn * 4 + 1];
                float b2 = Bs[kk][tn * 4 + 2];
                float b3 = Bs[kk][tn * 4 + 3];
                acc[0][0] += a0 * b0; acc[0][1] += a0 * b1; acc[0][2] += a0 * b2; acc[0][3] += a0 * b3;
                acc[1][0] += a1 * b0; acc[1][1] += a1 * b1; acc[1][2] += a1 * b2; acc[1][3] += a1 * b3;
                acc[2][0] += a2 * b0; acc[2][1] += a2 * b1; acc[2][2] += a2 * b2; acc[2][3] += a2 * b3;
                acc[3][0] += a3 * b0; acc[3][1] += a3 * b1; acc[3][2] += a3 * b2; acc[3][3] += a3 * b3;
            }
            __syncthreads();
        }
    }
    #pragma unroll
    for (int i2 = 0; i2 < 4; i2++) {
        int row = bm + tm * 4 + i2;
        float4 v;
        v.x = acc[i2][0]; v.y = acc[i2][1]; v.z = acc[i2][2]; v.w = acc[i2][3];
        *(float4*)(g_y + (long)row * H + bn + tn * 4) = v;
    }
}

// =====================================================================
// BN stats: per-channel sum / sumsq over all (b,s) rows of g_y
// grid (12, 32), block 256 = (64 channels, 4 row-groups of 32 rows)
// =====================================================================
__global__ void stats_kernel() {
    int idx = g_index;
    if (idx < 3 || idx > 8) return;
    int tx = threadIdx.x & 63;
    int ty = threadIdx.x >> 6;
    int c = blockIdx.x * 64 + tx;
    int r0 = blockIdx.y * 128 + ty * 32;
    float s = 0.f, s2 = 0.f;
    #pragma unroll 4
    for (int rr = 0; rr < 32; rr++) {
        float v = g_y[(long)(r0 + rr) * H + c];
        s += v; s2 += v * v;
    }
    __shared__ float sh[4][64], sh2[4][64];
    sh[ty][tx] = s; sh2[ty][tx] = s2;
    __syncthreads();
    if (ty == 0) {
        s  = sh[0][tx] + sh[1][tx] + sh[2][tx] + sh[3][tx];
        s2 = sh2[0][tx] + sh2[1][tx] + sh2[2][tx] + sh2[3][tx];
        atomicAdd(&g_sum[c], s);
        atomicAdd(&g_sumsq[c], s2);
    }
}

// =====================================================================
// BN normalize + gate scale + residual + output
// =====================================================================
__global__ void bn_out_kernel(const float* __restrict__ x,
                              const float* __restrict__ gn3, const float* __restrict__ bn3,
                              const float* __restrict__ gn5, const float* __restrict__ bn5,
                              const float* __restrict__ gn7, const float* __restrict__ bn7,
                              const float* __restrict__ gd3, const float* __restrict__ bd3,
                              const float* __restrict__ gd5, const float* __restrict__ bd5,
                              const float* __restrict__ gd7, const float* __restrict__ bd7,
                              float* __restrict__ out) {
    int idx = g_index;
    if (idx < 3 || idx > 8) return;
    const float *ga, *be;
    switch (idx) {
        case 3: ga = gn3; be = bn3; break;
        case 4: ga = gn5; be = bn5; break;
        case 5: ga = gn7; be = bn7; break;
        case 6: ga = gd3; be = bd3; break;
        case 7: ga = gd5; be = bd5; break;
        default: ga = gd7; be = bd7; break;
    }
    float w = g_wsel;
    const float invN = 1.f / (float)M_ROWS;
    const float4* x4 = (const float4*)x;
    const float4* y4 = (const float4*)g_y;
    float4* o4 = (float4*)out;
    for (int v = blockIdx.x * blockDim.x + threadIdx.x; v < NVEC;
         v += gridDim.x * blockDim.x) {
        int c0 = (v % H4) * 4;
        float4 yv = y4[v];
        float4 xv = x4[v];
        float4 r;
        {
            float mean = g_sum[c0] * invN;
            float var = g_sumsq[c0] * invN - mean * mean;
            float inv = rsqrtf(var + 1e-5f);
            r.x = w * ((yv.x - mean) * inv * ga[c0] + be[c0]) + xv.x;
        }
        {
            float mean = g_sum[c0 + 1] * invN;
            float var = g_sumsq[c0 + 1] * invN - mean * mean;
            float inv = rsqrtf(var + 1e-5f);
            r.y = w * ((yv.y - mean) * inv * ga[c0 + 1] + be[c0 + 1]) + xv.y;
        }
        {
            float mean = g_sum[c0 + 2] * invN;
            float var = g_sumsq[c0 + 2] * invN - mean * mean;
            float inv = rsqrtf(var + 1e-5f);
            r.z = w * ((yv.z - mean) * inv * ga[c0 + 2] + be[c0 + 2]) + xv.z;
        }
        {
            float mean = g_sum[c0 + 3] * invN;
            float var = g_sumsq[c0 + 3] * invN - mean * mean;
            float inv = rsqrtf(var + 1e-5f);
            r.w = w * ((yv.w - mean) * inv * ga[c0 + 3] + be[c0 + 3]) + xv.w;
        }
        o4[v] = r;
    }
}

// =====================================================================
extern "C" void kernel_launch(void* const* d_in, const int* in_sizes, int n_in,
                              void* d_out, int out_size) {
    const float* x     = (const float*)d_in[0];
    const float* u     = (const float*)d_in[1];
    const float* arch  = (const float*)d_in[2];
    const float* w_nor3 = (const float*)d_in[3];
    const float* g_nor3 = (const float*)d_in[4];
    const float* b_nor3 = (const float*)d_in[5];
    const float* w_nor5 = (const float*)d_in[6];
    const float* g_nor5 = (const float*)d_in[7];
    const float* b_nor5 = (const float*)d_in[8];
    const float* w_nor7 = (const float*)d_in[9];
    const float* g_nor7 = (const float*)d_in[10];
    const float* b_nor7 = (const float*)d_in[11];
    const float* wd_dil3 = (const float*)d_in[12];
    const float* wp_dil3 = (const float*)d_in[13];
    const float* g_dil3  = (const float*)d_in[14];
    const float* b_dil3  = (const float*)d_in[15];
    const float* wd_dil5 = (const float*)d_in[16];
    const float* wp_dil5 = (const float*)d_in[17];
    const float* g_dil5  = (const float*)d_in[18];
    const float* b_dil5  = (const float*)d_in[19];
    const float* wd_dil7 = (const float*)d_in[20];
    const float* wp_dil7 = (const float*)d_in[21];
    const float* g_dil7  = (const float*)d_in[22];
    const float* b_dil7  = (const float*)d_in[23];
    float* out = (float*)d_out;

    gate_kernel<<<1, 256>>>(arch, u);
    // conv path (no-ops if a simple branch is selected)
    pack_kernel<<<2048, 256>>>(w_nor3, w_nor5, w_nor7, wp_dil3, wp_dil5, wp_dil7);
    depthwise_kernel<<<2048, 256>>>(x, wd_dil3, wd_dil5, wd_dil7);
    gemm_kernel<<<dim3(64, 12), 256>>>(x);
    stats_kernel<<<dim3(12, 32), 256>>>();
    bn_out_kernel<<<2048, 256>>>(x, g_nor3, b_nor3, g_nor5, b_nor5, g_nor7, b_nor7,
                                 g_dil3, b_dil3, g_dil5, b_dil5, g_dil7, b_dil7, out);
    // simple path (no-op if a conv branch is selected)
    simple_kernel<<<2048, 256>>>(x, out);
}

// round 2
// speedup vs baseline: 1.4987x; 1.4987x over previous
#include <cuda_runtime.h>
#include <math.h>

#define H 768
#define H4 (H/4)
#define SLEN 512
#define BATCH 8
#define M_ROWS (BATCH*SLEN)        // 4096
#define NELEM (BATCH*SLEN*H)       // 3145728
#define NVEC (NELEM/4)             // 786432

// ---- device globals (scratch; no allocation allowed) ----
__device__ int   g_index;
__device__ float g_wsel;
__device__ float g_sum[H];
__device__ float g_sumsq[H];
__device__ float g_y[NELEM];        // conv output scratch [b,s,o]
__device__ float g_y1[NELEM];       // depthwise output scratch [b,s,c]
__device__ float g_wpack[H*H*7];    // packed weights [(dk*H + i)*H + o]

// =====================================================================
// Inline gate: gumbel straight-through argmax (computed by thread 0,
// broadcast via shared). ~10 loads + ~40 MUFU; negligible per block.
// =====================================================================
__device__ __forceinline__ void gate_compute(const float* __restrict__ arch,
                                             const float* __restrict__ u,
                                             int* s_idx, float* s_w) {
    if (threadIdx.x == 0) {
        float a[10], l[10], p[10];
        float m = -1e30f;
        #pragma unroll
        for (int j = 0; j < 10; j++) { a[j] = arch[j]; m = fmaxf(m, a[j]); }
        float se = 0.f;
        #pragma unroll
        for (int j = 0; j < 10; j++) se += expf(a[j] - m);
        float lse = logf(se);
        float m2 = -1e30f;
        #pragma unroll
        for (int j = 0; j < 10; j++) {
            float uc = u[j];
            uc = fminf(fmaxf(uc, 1e-9f), 1.0f - 1e-9f);
            float g = -logf(-logf(uc));
            l[j] = ((a[j] - m - lse) + g) * 0.1f;   // / TEM (=10)
            m2 = fmaxf(m2, l[j]);
        }
        float s2 = 0.f;
        #pragma unroll
        for (int j = 0; j < 10; j++) { p[j] = expf(l[j] - m2); s2 += p[j]; }
        int best = 0; float bp = -1.f;
        #pragma unroll
        for (int j = 0; j < 10; j++) {
            p[j] /= s2;
            if (p[j] > bp) { bp = p[j]; best = j; }
        }
        *s_idx = best;
        // hardwts[best] = (1-p)+p; off-index entries exactly 0 => out = w*op(x)+x
        *s_w = (1.0f - bp) + bp;
    }
    __syncthreads();
}

// =====================================================================
// Kernel 1: prep. All blocks compute gate inline. Block 0 publishes
// g_index/g_wsel + zeroes stats. Conv branches: weight pack (+ depthwise
// for dil branches). Simple branches: exit (~1 wave of tiny blocks).
// =====================================================================
__global__ void prep_kernel(const float* __restrict__ x,
                            const float* __restrict__ arch,
                            const float* __restrict__ u,
                            const float* __restrict__ wn3,
                            const float* __restrict__ wn5,
                            const float* __restrict__ wn7,
                            const float* __restrict__ wd3,
                            const float* __restrict__ wd5,
                            const float* __restrict__ wd7,
                            const float* __restrict__ wp3,
                            const float* __restrict__ wp5,
                            const float* __restrict__ wp7) {
    __shared__ int sidx; __shared__ float swsel;
    gate_compute(arch, u, &sidx, &swsel);
    int idx = sidx;
    if (blockIdx.x == 0) {
        if (threadIdx.x == 0) { g_index = idx; g_wsel = swsel; }
        for (int c = threadIdx.x; c < H; c += blockDim.x) { g_sum[c] = 0.f; g_sumsq[c] = 0.f; }
    }
    if (idx < 3 || idx > 8) return;

    // ---- weight pack: [(o*H+i)*taps+dk] -> [(dk*H+i)*H+o] ----
    const float* W; int taps;
    switch (idx) {
        case 3: W = wn3; taps = 3; break;
        case 4: W = wn5; taps = 5; break;
        case 5: W = wn7; taps = 7; break;
        case 6: W = wp3; taps = 1; break;
        case 7: W = wp5; taps = 1; break;
        default: W = wp7; taps = 1; break;
    }
    int total = H * H * taps;
    for (int e = blockIdx.x * blockDim.x + threadIdx.x; e < total;
         e += gridDim.x * blockDim.x) {
        int o  = e % H;
        int i  = (e / H) % H;
        int dk = e / (H * H);
        g_wpack[e] = W[(o * H + i) * taps + dk];
    }

    // ---- depthwise dilated conv (branches 6..8) ----
    if (idx >= 6) {
        int k = 3 + 2 * (idx - 6);
        const float* wd = (idx == 6) ? wd3 : ((idx == 7) ? wd5 : wd7);
        const float4* x4 = (const float4*)x;
        float4* y14 = (float4*)g_y1;
        for (int v = blockIdx.x * blockDim.x + threadIdx.x; v < NVEC;
             v += gridDim.x * blockDim.x) {
            int c4 = v % H4;
            int s  = (v / H4) % SLEN;
            int b  = v / (H4 * SLEN);
            int c0 = c4 * 4;
            float4 acc = make_float4(0.f, 0.f, 0.f, 0.f);
            for (int dk = 0; dk < k; dk++) {
                int s2 = s + 2 * dk - (k - 1);
                if (s2 < 0 || s2 >= SLEN) continue;
                float4 xv = x4[(long)(b * SLEN + s2) * H4 + c4];
                xv.x = fmaxf(xv.x, 0.f); xv.y = fmaxf(xv.y, 0.f);
                xv.z = fmaxf(xv.z, 0.f); xv.w = fmaxf(xv.w, 0.f);
                acc.x += wd[(c0 + 0) * k + dk] * xv.x;
                acc.y += wd[(c0 + 1) * k + dk] * xv.y;
                acc.z += wd[(c0 + 2) * k + dk] * xv.z;
                acc.w += wd[(c0 + 3) * k + dk] * xv.w;
            }
            y14[v] = acc;
        }
    }
}

// =====================================================================
// Kernel 2: GEMM + fused BN stats.
// Y[(b,s), o] = sum_dk sum_i act(A[(b,s+dk-pad), i]) * W[o,i,dk]
// Tile 64x64, BK=16, 256 threads, 4x4 per thread. After the mainloop each
// tile reduces its per-column sum/sumsq through shared and atomicAdds
// into g_sum/g_sumsq (replaces the separate stats kernel).
// =====================================================================
__global__ void gemm_kernel(const float* __restrict__ x) {
    int idx = g_index;
    if (idx < 3 || idx > 8) return;
    bool is_nor = (idx <= 5);
    int taps = is_nor ? (3 + 2 * (idx - 3)) : 1;
    int pad  = is_nor ? (taps >> 1) : 0;
    const float* A = is_nor ? x : (const float*)g_y1;

    __shared__ float As[16][64];
    __shared__ float Bs[16][64];

    int tid = threadIdx.x;
    int bm = blockIdx.x * 64, bn = blockIdx.y * 64;
    int tm = tid >> 4, tn = tid & 15;

    float acc[4][4] = {};

    int ar = tid & 63;           // A row within tile
    int ac = (tid >> 6) << 2;    // 4 consecutive k's
    int grow = bm + ar;
    int bb = grow >> 9, ss = grow & 511;
    int bkk = tid >> 4;          // B: k index
    int boc = (tid & 15) << 2;   // B: 4 consecutive o's

    for (int dk = 0; dk < taps; dk++) {
        int s2 = ss + dk - pad;
        bool valid = (s2 >= 0 && s2 < SLEN);
        const float* arow = A + (long)((bb << 9) + s2) * H;
        const float* bbase = g_wpack + (long)dk * H * H;
        for (int kt = 0; kt < H; kt += 16) {
            if (valid) {
                float4 v = *(const float4*)(arow + kt + ac);
                if (is_nor) {
                    v.x = fmaxf(v.x, 0.f); v.y = fmaxf(v.y, 0.f);
                    v.z = fmaxf(v.z, 0.f); v.w = fmaxf(v.w, 0.f);
                }
                As[ac][ar] = v.x; As[ac + 1][ar] = v.y;
                As[ac + 2][ar] = v.z; As[ac + 3][ar] = v.w;
            } else {
                As[ac][ar] = 0.f; As[ac + 1][ar] = 0.f;
                As[ac + 2][ar] = 0.f; As[ac + 3][ar] = 0.f;
            }
            float4 w4 = *(const float4*)(bbase + (long)(kt + bkk) * H + bn + boc);
            Bs[bkk][boc] = w4.x; Bs[bkk][boc + 1] = w4.y;
            Bs[bkk][boc + 2] = w4.z; Bs[bkk][boc + 3] = w4.w;
            __syncthreads();
            #pragma unroll
            for (int kk = 0; kk < 16; kk++) {
                float a0 = As[kk][tm * 4 + 0];
                float a1 = As[kk][tm * 4 + 1];
                float a2 = As[kk][tm * 4 + 2];
                float a3 = As[kk][tm * 4 + 3];
                float b0 = Bs[kk][tn * 4 + 0];
                float b1 = Bs[kk][tn * 4 + 1];
                float b2 = Bs[kk][tn * 4 + 2];
                float b3 = Bs[kk][tn * 4 + 3];
                acc[0][0] += a0 * b0; acc[0][1] += a0 * b1; acc[0][2] += a0 * b2; acc[0][3] += a0 * b3;
                acc[1][0] += a1 * b0; acc[1][1] += a1 * b1; acc[1][2] += a1 * b2; acc[1][3] += a1 * b3;
                acc[2][0] += a2 * b0; acc[2][1] += a2 * b1; acc[2][2] += a2 * b2; acc[2][3] += a2 * b3;
                acc[3][0] += a3 * b0; acc[3][1] += a3 * b1; acc[3][2] += a3 * b2; acc[3][3] += a3 * b3;
            }
            __syncthreads();
        }
    }
    // write output tile
    #pragma unroll
    for (int i2 = 0; i2 < 4; i2++) {
        int row = bm + tm * 4 + i2;
        float4 v;
        v.x = acc[i2][0]; v.y = acc[i2][1]; v.z = acc[i2][2]; v.w = acc[i2][3];
        *(float4*)(g_y + (long)row * H + bn + tn * 4) = v;
    }
    // fused BN stats: per-column sum / sumsq for this 64x64 tile
    float cs[4], cq[4];
    #pragma unroll
    for (int j = 0; j < 4; j++) {
        cs[j] = acc[0][j] + acc[1][j] + acc[2][j] + acc[3][j];
        cq[j] = acc[0][j] * acc[0][j] + acc[1][j] * acc[1][j]
              + acc[2][j] * acc[2][j] + acc[3][j] * acc[3][j];
    }
    #pragma unroll
    for (int j = 0; j < 4; j++) { As[tm][tn * 4 + j] = cs[j]; Bs[tm][tn * 4 + j] = cq[j]; }
    __syncthreads();
    if (tid < 64) {
        float s = 0.f, q = 0.f;
        #pragma unroll
        for (int r = 0; r < 16; r++) { s += As[r][tid]; q += Bs[r][tid]; }
        atomicAdd(&g_sum[bn + tid], s);
        atomicAdd(&g_sumsq[bn + tid], q);
    }
}

// =====================================================================
// Kernel 3: epilogue. Handles BOTH paths:
//   simple branches (0/1/2/9): pool/skip/none + gate scale + residual
//   conv branches (3..8): BN (per-block precomputed scale/shift) +
//                         gate scale + residual
// =====================================================================
__global__ void epilogue_kernel(const float* __restrict__ x,
                                const float* __restrict__ gn3, const float* __restrict__ bn3,
                                const float* __restrict__ gn5, const float* __restrict__ bn5,
                                const float* __restrict__ gn7, const float* __restrict__ bn7,
                                const float* __restrict__ gd3, const float* __restrict__ bd3,
                                const float* __restrict__ gd5, const float* __restrict__ bd5,
                                const float* __restrict__ gd7, const float* __restrict__ bd7,
                                float* __restrict__ out) {
    int idx = g_index;
    float w = g_wsel;
    const float4* x4 = (const float4*)x;
    float4* o4 = (float4*)out;

    if (idx >= 3 && idx <= 8) {
        // ---- BN path ----
        const float *ga, *be;
        switch (idx) {
            case 3: ga = gn3; be = bn3; break;
            case 4: ga = gn5; be = bn5; break;
            case 5: ga = gn7; be = bn7; break;
            case 6: ga = gd3; be = bd3; break;
            case 7: ga = gd5; be = bd5; break;
            default: ga = gd7; be = bd7; break;
        }
        __shared__ float s_scale[H], s_shift[H];
        const float invN = 1.f / (float)M_ROWS;
        for (int c = threadIdx.x; c < H; c += blockDim.x) {
            float mean = g_sum[c] * invN;
            float var  = g_sumsq[c] * invN - mean * mean;
            float inv  = rsqrtf(var + 1e-5f);
            float sc   = w * ga[c] * inv;
            s_scale[c] = sc;
            s_shift[c] = w * be[c] - mean * sc;
        }
        __syncthreads();
        const float4* y4 = (const float4*)g_y;
        for (int v = blockIdx.x * blockDim.x + threadIdx.x; v < NVEC;
             v += gridDim.x * blockDim.x) {
            int c0 = (v % H4) * 4;
            float4 yv = y4[v];
            float4 xv = x4[v];
            float4 r;
            r.x = s_scale[c0 + 0] * yv.x + s_shift[c0 + 0] + xv.x;
            r.y = s_scale[c0 + 1] * yv.y + s_shift[c0 + 1] + xv.y;
            r.z = s_scale[c0 + 2] * yv.z + s_shift[c0 + 2] + xv.z;
            r.w = s_scale[c0 + 3] * yv.w + s_shift[c0 + 3] + xv.w;
            o4[v] = r;
        }
    } else {
        // ---- simple path ----
        for (int v = blockIdx.x * blockDim.x + threadIdx.x; v < NVEC;
             v += gridDim.x * blockDim.x) {
            int c4 = v % H4;
            int s  = (v / H4) % SLEN;
            int b  = v / (H4 * SLEN);
            float4 xc = x4[v];
            float4 val;
            if (idx == 0) {
                val = make_float4(0.f, 0.f, 0.f, 0.f);
            } else if (idx == 9) {
                val = xc;
            } else {
                long base = (long)(b * SLEN) * H4 + c4;
                float4 xm = make_float4(0.f, 0.f, 0.f, 0.f);
                float4 xp = make_float4(0.f, 0.f, 0.f, 0.f);
                bool hm = (s > 0), hp = (s < SLEN - 1);
                if (hm) xm = x4[base + (long)(s - 1) * H4];
                if (hp) xp = x4[base + (long)(s + 1) * H4];
                if (idx == 1) {       // avg, count_include_pad
                    const float inv3 = 1.f / 3.f;
                    val.x = (xm.x + xc.x + xp.x) * inv3;
                    val.y = (xm.y + xc.y + xp.y) * inv3;
                    val.z = (xm.z + xc.z + xp.z) * inv3;
                    val.w = (xm.w + xc.w + xp.w) * inv3;
                } else {              // max, -inf pad -> only valid neighbors
                    val = xc;
                    if (hm) { val.x = fmaxf(val.x, xm.x); val.y = fmaxf(val.y, xm.y);
                              val.z = fmaxf(val.z, xm.z); val.w = fmaxf(val.w, xm.w); }
                    if (hp) { val.x = fmaxf(val.x, xp.x); val.y = fmaxf(val.y, xp.y);
                              val.z = fmaxf(val.z, xp.z); val.w = fmaxf(val.w, xp.w); }
                }
            }
            float4 r;
            r.x = w * val.x + xc.x;
            r.y = w * val.y + xc.y;
            r.z = w * val.z + xc.z;
            r.w = w * val.w + xc.w;
            o4[v] = r;
        }
    }
}

// =====================================================================
extern "C" void kernel_launch(void* const* d_in, const int* in_sizes, int n_in,
                              void* d_out, int out_size) {
    const float* x     = (const float*)d_in[0];
    const float* u     = (const float*)d_in[1];
    const float* arch  = (const float*)d_in[2];
    const float* w_nor3 = (const float*)d_in[3];
    const float* g_nor3 = (const float*)d_in[4];
    const float* b_nor3 = (const float*)d_in[5];
    const float* w_nor5 = (const float*)d_in[6];
    const float* g_nor5 = (const float*)d_in[7];
    const float* b_nor5 = (const float*)d_in[8];
    const float* w_nor7 = (const float*)d_in[9];
    const float* g_nor7 = (const float*)d_in[10];
    const float* b_nor7 = (const float*)d_in[11];
    const float* wd_dil3 = (const float*)d_in[12];
    const float* wp_dil3 = (const float*)d_in[13];
    const float* g_dil3  = (const float*)d_in[14];
    const float* b_dil3  = (const float*)d_in[15];
    const float* wd_dil5 = (const float*)d_in[16];
    const float* wp_dil5 = (const float*)d_in[17];
    const float* g_dil5  = (const float*)d_in[18];
    const float* b_dil5  = (const float*)d_in[19];
    const float* wd_dil7 = (const float*)d_in[20];
    const float* wp_dil7 = (const float*)d_in[21];
    const float* g_dil7  = (const float*)d_in[22];
    const float* b_dil7  = (const float*)d_in[23];
    float* out = (float*)d_out;

    prep_kernel<<<864, 256>>>(x, arch, u,
                              w_nor3, w_nor5, w_nor7,
                              wd_dil3, wd_dil5, wd_dil7,
                              wp_dil3, wp_dil5, wp_dil7);
    gemm_kernel<<<dim3(64, 12), 256>>>(x);
    epilogue_kernel<<<1024, 256>>>(x, g_nor3, b_nor3, g_nor5, b_nor5, g_nor7, b_nor7,
                                   g_dil3, b_dil3, g_dil5, b_dil5, g_dil7, b_dil7, out);
}

// round 3
// speedup vs baseline: 1.7434x; 1.1633x over previous
#include <cuda_runtime.h>
#include <math.h>

#define H 768
#define H4 (H/4)
#define SLEN 512
#define BATCH 8
#define M_ROWS (BATCH*SLEN)        // 4096
#define NELEM (BATCH*SLEN*H)       // 3145728
#define NVEC (NELEM/4)             // 786432

// ---- device globals (scratch; no allocation allowed) ----
__device__ int   g_index;
__device__ float g_wsel;
__device__ float g_sum[H];
__device__ float g_sumsq[H];
__device__ float g_y[NELEM];        // conv output scratch [b,s,o]
__device__ float g_y1[NELEM];       // depthwise output scratch [b,s,c]
__device__ float g_wpack[H*H*7];    // packed weights [(dk*H + i)*H + o]

// =====================================================================
// Warp-parallel gate: lanes 0..9 each own one branch. 2 parallel loads,
// shuffle reductions. ~300 dependent cycles instead of ~5000.
// Straight-through: off-index hardwts are exactly 0, selected is (1-p)+p,
// so out = w_sel * op(x) + x.
// =====================================================================
__device__ __forceinline__ void gate_warp(const float* __restrict__ arch,
                                          const float* __restrict__ u,
                                          int* s_idx, float* s_w) {
    if (threadIdx.x < 32) {
        int lane = threadIdx.x;
        bool act = (lane < 10);
        float a  = act ? __ldg(arch + lane) : -1e30f;
        float uu = act ? __ldg(u + lane) : 0.5f;
        // max over logits
        float m = a;
        #pragma unroll
        for (int o = 16; o > 0; o >>= 1) m = fmaxf(m, __shfl_xor_sync(0xffffffffu, m, o));
        // logsumexp
        float e = act ? expf(a - m) : 0.f;
        float se = e;
        #pragma unroll
        for (int o = 16; o > 0; o >>= 1) se += __shfl_xor_sync(0xffffffffu, se, o);
        float lse = logf(se);
        // gumbel
        float uc = fminf(fmaxf(uu, 1e-9f), 1.0f - 1e-9f);
        float g  = -logf(-logf(uc));
        float l  = act ? ((a - m - lse) + g) * 0.1f : -1e30f;   // / TEM(=10)
        // softmax over l
        float m2 = l;
        #pragma unroll
        for (int o = 16; o > 0; o >>= 1) m2 = fmaxf(m2, __shfl_xor_sync(0xffffffffu, m2, o));
        float p = act ? expf(l - m2) : 0.f;
        float s2 = p;
        #pragma unroll
        for (int o = 16; o > 0; o >>= 1) s2 += __shfl_xor_sync(0xffffffffu, s2, o);
        p /= s2;
        // argmax (lowest index on tie, matching jnp.argmax)
        float bp = p; int bi = lane;
        #pragma unroll
        for (int o = 16; o > 0; o >>= 1) {
            float op = __shfl_xor_sync(0xffffffffu, bp, o);
            int   oi = __shfl_xor_sync(0xffffffffu, bi, o);
            if (op > bp || (op == bp && oi < bi)) { bp = op; bi = oi; }
        }
        if (lane == 0) { *s_idx = bi; *s_w = (1.0f - bp) + bp; }
    }
    __syncthreads();
}

// =====================================================================
// Kernel 1: prep. All blocks compute gate (warp-parallel, cheap). Block 0
// publishes g_index/g_wsel + zeroes stats. Conv branches: weight pack
// (+ depthwise for dil branches). Simple branches: early exit.
// =====================================================================
__global__ void prep_kernel(const float* __restrict__ x,
                            const float* __restrict__ arch,
                            const float* __restrict__ u,
                            const float* __restrict__ wn3,
                            const float* __restrict__ wn5,
                            const float* __restrict__ wn7,
                            const float* __restrict__ wd3,
                            const float* __restrict__ wd5,
                            const float* __restrict__ wd7,
                            const float* __restrict__ wp3,
                            const float* __restrict__ wp5,
                            const float* __restrict__ wp7) {
    __shared__ int sidx; __shared__ float swsel;
    gate_warp(arch, u, &sidx, &swsel);
    int idx = sidx;
    if (blockIdx.x == 0) {
        if (threadIdx.x == 0) { g_index = idx; g_wsel = swsel; }
        for (int c = threadIdx.x; c < H; c += blockDim.x) { g_sum[c] = 0.f; g_sumsq[c] = 0.f; }
    }
    if (idx < 3 || idx > 8) return;

    // ---- weight pack: [(o*H+i)*taps+dk] -> [(dk*H+i)*H+o] ----
    const float* W; int taps;
    switch (idx) {
        case 3: W = wn3; taps = 3; break;
        case 4: W = wn5; taps = 5; break;
        case 5: W = wn7; taps = 7; break;
        case 6: W = wp3; taps = 1; break;
        case 7: W = wp5; taps = 1; break;
        default: W = wp7; taps = 1; break;
    }
    int total = H * H * taps;
    for (int e = blockIdx.x * blockDim.x + threadIdx.x; e < total;
         e += gridDim.x * blockDim.x) {
        int o  = e % H;
        int i  = (e / H) % H;
        int dk = e / (H * H);
        g_wpack[e] = W[(o * H + i) * taps + dk];
    }

    // ---- depthwise dilated conv (branches 6..8) ----
    if (idx >= 6) {
        int k = 3 + 2 * (idx - 6);
        const float* wd = (idx == 6) ? wd3 : ((idx == 7) ? wd5 : wd7);
        const float4* x4 = (const float4*)x;
        float4* y14 = (float4*)g_y1;
        for (int v = blockIdx.x * blockDim.x + threadIdx.x; v < NVEC;
             v += gridDim.x * blockDim.x) {
            int c4 = v % H4;
            int s  = (v / H4) % SLEN;
            int b  = v / (H4 * SLEN);
            int c0 = c4 * 4;
            float4 acc = make_float4(0.f, 0.f, 0.f, 0.f);
            for (int dk = 0; dk < k; dk++) {
                int s2 = s + 2 * dk - (k - 1);
                if (s2 < 0 || s2 >= SLEN) continue;
                float4 xv = x4[(long)(b * SLEN + s2) * H4 + c4];
                xv.x = fmaxf(xv.x, 0.f); xv.y = fmaxf(xv.y, 0.f);
                xv.z = fmaxf(xv.z, 0.f); xv.w = fmaxf(xv.w, 0.f);
                acc.x += wd[(c0 + 0) * k + dk] * xv.x;
                acc.y += wd[(c0 + 1) * k + dk] * xv.y;
                acc.z += wd[(c0 + 2) * k + dk] * xv.z;
                acc.w += wd[(c0 + 3) * k + dk] * xv.w;
            }
            y14[v] = acc;
        }
    }
}

// =====================================================================
// Kernel 2: GEMM + fused BN stats (conv branches only; dead-exit else).
// Tile 64x64, BK=16, 256 threads, 4x4 per thread.
// =====================================================================
__global__ void gemm_kernel(const float* __restrict__ x) {
    int idx = g_index;
    if (idx < 3 || idx > 8) return;
    bool is_nor = (idx <= 5);
    int taps = is_nor ? (3 + 2 * (idx - 3)) : 1;
    int pad  = is_nor ? (taps >> 1) : 0;
    const float* A = is_nor ? x : (const float*)g_y1;

    __shared__ float As[16][64];
    __shared__ float Bs[16][64];

    int tid = threadIdx.x;
    int bm = blockIdx.x * 64, bn = blockIdx.y * 64;
    int tm = tid >> 4, tn = tid & 15;

    float acc[4][4] = {};

    int ar = tid & 63;           // A row within tile
    int ac = (tid >> 6) << 2;    // 4 consecutive k's
    int grow = bm + ar;
    int bb = grow >> 9, ss = grow & 511;
    int bkk = tid >> 4;          // B: k index
    int boc = (tid & 15) << 2;   // B: 4 consecutive o's

    for (int dk = 0; dk < taps; dk++) {
        int s2 = ss + dk - pad;
        bool valid = (s2 >= 0 && s2 < SLEN);
        const float* arow = A + (long)((bb << 9) + s2) * H;
        const float* bbase = g_wpack + (long)dk * H * H;
        for (int kt = 0; kt < H; kt += 16) {
            if (valid) {
                float4 v = *(const float4*)(arow + kt + ac);
                if (is_nor) {
                    v.x = fmaxf(v.x, 0.f); v.y = fmaxf(v.y, 0.f);
                    v.z = fmaxf(v.z, 0.f); v.w = fmaxf(v.w, 0.f);
                }
                As[ac][ar] = v.x; As[ac + 1][ar] = v.y;
                As[ac + 2][ar] = v.z; As[ac + 3][ar] = v.w;
            } else {
                As[ac][ar] = 0.f; As[ac + 1][ar] = 0.f;
                As[ac + 2][ar] = 0.f; As[ac + 3][ar] = 0.f;
            }
            float4 w4 = *(const float4*)(bbase + (long)(kt + bkk) * H + bn + boc);
            Bs[bkk][boc] = w4.x; Bs[bkk][boc + 1] = w4.y;
            Bs[bkk][boc + 2] = w4.z; Bs[bkk][boc + 3] = w4.w;
            __syncthreads();
            #pragma unroll
            for (int kk = 0; kk < 16; kk++) {
                float a0 = As[kk][tm * 4 + 0];
                float a1 = As[kk][tm * 4 + 1];
                float a2 = As[kk][tm * 4 + 2];
                float a3 = As[kk][tm * 4 + 3];
                float b0 = Bs[kk][tn * 4 + 0];
                float b1 = Bs[kk][tn * 4 + 1];
                float b2 = Bs[kk][tn * 4 + 2];
                float b3 = Bs[kk][tn * 4 + 3];
                acc[0][0] += a0 * b0; acc[0][1] += a0 * b1; acc[0][2] += a0 * b2; acc[0][3] += a0 * b3;
                acc[1][0] += a1 * b0; acc[1][1] += a1 * b1; acc[1][2] += a1 * b2; acc[1][3] += a1 * b3;
                acc[2][0] += a2 * b0; acc[2][1] += a2 * b1; acc[2][2] += a2 * b2; acc[2][3] += a2 * b3;
                acc[3][0] += a3 * b0; acc[3][1] += a3 * b1; acc[3][2] += a3 * b2; acc[3][3] += a3 * b3;
            }
            __syncthreads();
        }
    }
    #pragma unroll
    for (int i2 = 0; i2 < 4; i2++) {
        int row = bm + tm * 4 + i2;
        float4 v;
        v.x = acc[i2][0]; v.y = acc[i2][1]; v.z = acc[i2][2]; v.w = acc[i2][3];
        *(float4*)(g_y + (long)row * H + bn + tn * 4) = v;
    }
    // fused BN stats
    float cs[4], cq[4];
    #pragma unroll
    for (int j = 0; j < 4; j++) {
        cs[j] = acc[0][j] + acc[1][j] + acc[2][j] + acc[3][j];
        cq[j] = acc[0][j] * acc[0][j] + acc[1][j] * acc[1][j]
              + acc[2][j] * acc[2][j] + acc[3][j] * acc[3][j];
    }
    #pragma unroll
    for (int j = 0; j < 4; j++) { As[tm][tn * 4 + j] = cs[j]; Bs[tm][tn * 4 + j] = cq[j]; }
    __syncthreads();
    if (tid < 64) {
        float s = 0.f, q = 0.f;
        #pragma unroll
        for (int r = 0; r < 16; r++) { s += As[r][tid]; q += Bs[r][tid]; }
        atomicAdd(&g_sum[bn + tid], s);
        atomicAdd(&g_sumsq[bn + tid], q);
    }
}

// =====================================================================
// Kernel 3: epilogue. simple branches: pool/skip/none + residual.
// conv branches: BN with per-block precomputed scale/shift + residual.
// =====================================================================
__global__ void epilogue_kernel(const float* __restrict__ x,
                                const float* __restrict__ gn3, const float* __restrict__ bn3,
                                const float* __restrict__ gn5, const float* __restrict__ bn5,
                                const float* __restrict__ gn7, const float* __restrict__ bn7,
                                const float* __restrict__ gd3, const float* __restrict__ bd3,
                                const float* __restrict__ gd5, const float* __restrict__ bd5,
                                const float* __restrict__ gd7, const float* __restrict__ bd7,
                                float* __restrict__ out) {
    int idx = g_index;
    float w = g_wsel;
    const float4* x4 = (const float4*)x;
    float4* o4 = (float4*)out;

    if (idx >= 3 && idx <= 8) {
        const float *ga, *be;
        switch (idx) {
            case 3: ga = gn3; be = bn3; break;
            case 4: ga = gn5; be = bn5; break;
            case 5: ga = gn7; be = bn7; break;
            case 6: ga = gd3; be = bd3; break;
            case 7: ga = gd5; be = bd5; break;
            default: ga = gd7; be = bd7; break;
        }
        __shared__ float s_scale[H], s_shift[H];
        const float invN = 1.f / (float)M_ROWS;
        for (int c = threadIdx.x; c < H; c += blockDim.x) {
            float mean = g_sum[c] * invN;
            float var  = g_sumsq[c] * invN - mean * mean;
            float inv  = rsqrtf(var + 1e-5f);
            float sc   = w * ga[c] * inv;
            s_scale[c] = sc;
            s_shift[c] = w * be[c] - mean * sc;
        }
        __syncthreads();
        const float4* y4 = (const float4*)g_y;
        for (int v = blockIdx.x * blockDim.x + threadIdx.x; v < NVEC;
             v += gridDim.x * blockDim.x) {
            int c0 = (v % H4) * 4;
            float4 yv = y4[v];
            float4 xv = x4[v];
            float4 r;
            r.x = s_scale[c0 + 0] * yv.x + s_shift[c0 + 0] + xv.x;
            r.y = s_scale[c0 + 1] * yv.y + s_shift[c0 + 1] + xv.y;
            r.z = s_scale[c0 + 2] * yv.z + s_shift[c0 + 2] + xv.z;
            r.w = s_scale[c0 + 3] * yv.w + s_shift[c0 + 3] + xv.w;
            o4[v] = r;
        }
    } else {
        for (int v = blockIdx.x * blockDim.x + threadIdx.x; v < NVEC;
             v += gridDim.x * blockDim.x) {
            int c4 = v % H4;
            int s  = (v / H4) % SLEN;
            int b  = v / (H4 * SLEN);
            float4 xc = x4[v];
            float4 val;
            if (idx == 0) {
                val = make_float4(0.f, 0.f, 0.f, 0.f);
            } else if (idx == 9) {
                val = xc;
            } else {
                long base = (long)(b * SLEN) * H4 + c4;
                float4 xm = make_float4(0.f, 0.f, 0.f, 0.f);
                float4 xp = make_float4(0.f, 0.f, 0.f, 0.f);
                bool hm = (s > 0), hp = (s < SLEN - 1);
                if (hm) xm = x4[base + (long)(s - 1) * H4];
                if (hp) xp = x4[base + (long)(s + 1) * H4];
                if (idx == 1) {       // avg, count_include_pad
                    const float inv3 = 1.f / 3.f;
                    val.x = (xm.x + xc.x + xp.x) * inv3;
                    val.y = (xm.y + xc.y + xp.y) * inv3;
                    val.z = (xm.z + xc.z + xp.z) * inv3;
                    val.w = (xm.w + xc.w + xp.w) * inv3;
                } else {              // max, -inf pad -> only valid neighbors
                    val = xc;
                    if (hm) { val.x = fmaxf(val.x, xm.x); val.y = fmaxf(val.y, xm.y);
                              val.z = fmaxf(val.z, xm.z); val.w = fmaxf(val.w, xm.w); }
                    if (hp) { val.x = fmaxf(val.x, xp.x); val.y = fmaxf(val.y, xp.y);
                              val.z = fmaxf(val.z, xp.z); val.w = fmaxf(val.w, xp.w); }
                }
            }
            float4 r;
            r.x = w * val.x + xc.x;
            r.y = w * val.y + xc.y;
            r.z = w * val.z + xc.z;
            r.w = w * val.w + xc.w;
            o4[v] = r;
        }
    }
}

// =====================================================================
extern "C" void kernel_launch(void* const* d_in, const int* in_sizes, int n_in,
                              void* d_out, int out_size) {
    const float* x     = (const float*)d_in[0];
    const float* u     = (const float*)d_in[1];
    const float* arch  = (const float*)d_in[2];
    const float* w_nor3 = (const float*)d_in[3];
    const float* g_nor3 = (const float*)d_in[4];
    const float* b_nor3 = (const float*)d_in[5];
    const float* w_nor5 = (const float*)d_in[6];
    const float* g_nor5 = (const float*)d_in[7];
    const float* b_nor5 = (const float*)d_in[8];
    const float* w_nor7 = (const float*)d_in[9];
    const float* g_nor7 = (const float*)d_in[10];
    const float* b_nor7 = (const float*)d_in[11];
    const float* wd_dil3 = (const float*)d_in[12];
    const float* wp_dil3 = (const float*)d_in[13];
    const float* g_dil3  = (const float*)d_in[14];
    const float* b_dil3  = (const float*)d_in[15];
    const float* wd_dil5 = (const float*)d_in[16];
    const float* wp_dil5 = (const float*)d_in[17];
    const float* g_dil5  = (const float*)d_in[18];
    const float* b_dil5  = (const float*)d_in[19];
    const float* wd_dil7 = (const float*)d_in[20];
    const float* wp_dil7 = (const float*)d_in[21];
    const float* g_dil7  = (const float*)d_in[22];
    const float* b_dil7  = (const float*)d_in[23];
    float* out = (float*)d_out;

    prep_kernel<<<864, 256>>>(x, arch, u,
                              w_nor3, w_nor5, w_nor7,
                              wd_dil3, wd_dil5, wd_dil7,
                              wp_dil3, wp_dil5, wp_dil7);
    gemm_kernel<<<dim3(64, 12), 256>>>(x);
    epilogue_kernel<<<1024, 256>>>(x, g_nor3, b_nor3, g_nor5, b_nor5, g_nor7, b_nor7,
                                   g_dil3, b_dil3, g_dil5, b_dil5, g_dil7, b_dil7, out);
}